// round 2
// baseline (speedup 1.0000x reference)
#include <cuda_runtime.h>
#include <math.h>

#define BATCH   2
#define SEQ     2048
#define DMODEL  1024
#define NHEADS  16
#define DHEAD   64
#define INNER   1024        // NHEADS*DKV
#define QKV3    3072        // 3*INNER

// -------- scratch (device globals; no allocation allowed) --------
__device__ float g_qkv[(size_t)BATCH * SEQ * QKV3];   // 48 MB : [b*s][3072] (q|k|v)
__device__ float g_ai [(size_t)BATCH * SEQ * INNER];  // 16 MB : attention inner output
__device__ float g_bias[NHEADS * 4096];               // 256 KB: bias[h][ (k-q)+2048 ]

// ---------------------------------------------------------------------------
// 1) Fill per-delta bias table: g_bias[h][delta+2048] = table[bucket(delta)][h]
//    Bucket math replicates the reference's float32 arithmetic exactly:
//    log computed in double then rounded to float32 (correctly rounded, same
//    as XLA's f32 log at the exact-boundary points ad=16,64,128).
// ---------------------------------------------------------------------------
__global__ void bias_fill_kernel(const float* __restrict__ table) {
    int idx = blockIdx.x * blockDim.x + threadIdx.x;  // 0..4095
    if (idx >= 4096) return;
    int rel = idx - 2048;                 // rel = k - q  (mem - ctx)
    int bucket = (rel > 0) ? 16 : 0;      // num_buckets//2 = 16
    int ad = rel < 0 ? -rel : rel;
    int bb;
    if (ad < 8) {
        bb = ad;
    } else {
        // reference (f32): (log(ad/8) / f32(log(16))) * 8, truncated to int
        float rp = (float)ad;
        float l  = (float)log((double)(rp / 8.0f));     // correctly-rounded f32 log
        float v  = (l / 2.7725887f) * 8.0f;             // f32(log(16)) = 4*f32(log(2))
        bb = 8 + (int)v;
        if (bb > 15) bb = 15;
    }
    bucket += bb;
    #pragma unroll
    for (int h = 0; h < NHEADS; h++)
        g_bias[h * 4096 + idx] = table[bucket * NHEADS + h];
}

// ---------------------------------------------------------------------------
// 2) Write position_bias output [1,16,2048,2048]
// ---------------------------------------------------------------------------
__global__ void bias_write_kernel(float* __restrict__ out) {
    int q = blockIdx.x;
    int h = blockIdx.y;
    int k = threadIdx.x << 2;  // 512 threads * 4 = 2048
    const float* src = g_bias + h * 4096 + (2048 - q) + k;
    float4 v = make_float4(src[0], src[1], src[2], src[3]);
    *(float4*)(out + ((size_t)h * SEQ + q) * SEQ + k) = v;
}

// ---------------------------------------------------------------------------
// 3) Classic 128x128x8 fp32 SGEMM: C[M,N] = A[M,K] @ B[K,N]
// ---------------------------------------------------------------------------
__global__ __launch_bounds__(256) void sgemm128_kernel(
    const float* __restrict__ A, const float* __restrict__ B,
    float* __restrict__ C, int M, int N, int K)
{
    __shared__ float As[8][128];   // transposed: As[k][m]
    __shared__ float Bs[8][128];   // Bs[k][n]
    int tid = threadIdx.x;
    int tx = tid & 15, ty = tid >> 4;
    int bm = blockIdx.y << 7, bn = blockIdx.x << 7;

    float acc[8][8];
    #pragma unroll
    for (int i = 0; i < 8; i++)
        #pragma unroll
        for (int j = 0; j < 8; j++) acc[i][j] = 0.f;

    int a_row = tid >> 1,  a_k = (tid & 1) << 2;
    int b_k   = tid >> 5,  b_n = (tid & 31) << 2;
    const float* Ap = A + (size_t)(bm + a_row) * K + a_k;
    const float* Bp = B + (size_t)b_k * N + bn + b_n;

    for (int k0 = 0; k0 < K; k0 += 8) {
        float4 av = *(const float4*)(Ap + k0);
        float4 bv = *(const float4*)(Bp + (size_t)k0 * N);
        __syncthreads();
        As[a_k + 0][a_row] = av.x;
        As[a_k + 1][a_row] = av.y;
        As[a_k + 2][a_row] = av.z;
        As[a_k + 3][a_row] = av.w;
        *(float4*)&Bs[b_k][b_n] = bv;
        __syncthreads();
        #pragma unroll
        for (int kk = 0; kk < 8; kk++) {
            float ar[8], br[8];
            *(float4*)&ar[0] = *(const float4*)&As[kk][(ty << 3)];
            *(float4*)&ar[4] = *(const float4*)&As[kk][(ty << 3) + 4];
            *(float4*)&br[0] = *(const float4*)&Bs[kk][(tx << 3)];
            *(float4*)&br[4] = *(const float4*)&Bs[kk][(tx << 3) + 4];
            #pragma unroll
            for (int i = 0; i < 8; i++)
                #pragma unroll
                for (int j = 0; j < 8; j++)
                    acc[i][j] += ar[i] * br[j];
        }
    }
    #pragma unroll
    for (int i = 0; i < 8; i++) {
        float* cp = C + (size_t)(bm + (ty << 3) + i) * N + bn + (tx << 3);
        *(float4*)cp       = make_float4(acc[i][0], acc[i][1], acc[i][2], acc[i][3]);
        *(float4*)(cp + 4) = make_float4(acc[i][4], acc[i][5], acc[i][6], acc[i][7]);
    }
}

// ---------------------------------------------------------------------------
// 4) Flash attention (fp32), 64x64 tiles, 4x4 frags, bias from g_bias (L2)
//    grid: (32 q-tiles, 16 heads, 2 batch), 256 threads
// ---------------------------------------------------------------------------
__global__ __launch_bounds__(256, 2) void attn_kernel() {
    __shared__ float Qs[64 * 64];   // Q[row][d]
    __shared__ float KP[64 * 64];   // K^T[d][k] during S; then P[row][k] during PV
    __shared__ float Vs[64 * 64];   // V[k][d]

    int tid = threadIdx.x;
    int tx = tid & 15, ty = tid >> 4;
    int q0 = blockIdx.x << 6;
    int h  = blockIdx.y;
    int b  = blockIdx.z;
    size_t base = (size_t)b * SEQ * QKV3;

    // bias: element (i,j) of frag at tile kb -> gb[k0 + j - i]
    const float* gb = g_bias + h * 4096 + 2048 - q0 + (tx << 2) - (ty << 2);

    // load Q tile
    #pragma unroll
    for (int j = 0; j < 4; j++) {
        int idx = (j << 8) + tid;
        int row = idx >> 4, c4 = (idx & 15) << 2;
        *(float4*)&Qs[(row << 6) + c4] =
            *(const float4*)&g_qkv[base + (size_t)(q0 + row) * QKV3 + h * DHEAD + c4];
    }

    float m_i[4], l_i[4], O[4][4];
    #pragma unroll
    for (int i = 0; i < 4; i++) {
        m_i[i] = -1e30f; l_i[i] = 0.f;
        #pragma unroll
        for (int j = 0; j < 4; j++) O[i][j] = 0.f;
    }

    for (int kb = 0; kb < 32; kb++) {
        int k0 = kb << 6;
        __syncthreads();   // previous PV finished reading KP/Vs
        // load K (transposed into KP) and V
        #pragma unroll
        for (int j = 0; j < 4; j++) {
            int idx = (j << 8) + tid;
            int row = idx >> 4, c4 = (idx & 15) << 2;
            const float* kp = &g_qkv[base + (size_t)(k0 + row) * QKV3 + INNER + h * DHEAD + c4];
            float4 kv = *(const float4*)kp;
            KP[((c4 + 0) << 6) + row] = kv.x;
            KP[((c4 + 1) << 6) + row] = kv.y;
            KP[((c4 + 2) << 6) + row] = kv.z;
            KP[((c4 + 3) << 6) + row] = kv.w;
            *(float4*)&Vs[(row << 6) + c4] = *(const float4*)(kp + INNER);
        }
        // bias fragment (L2-resident 256KB table); row i -> -i, col j -> +j
        float bf[4][4];
        #pragma unroll
        for (int i = 0; i < 4; i++)
            #pragma unroll
            for (int j = 0; j < 4; j++)
                bf[i][j] = __ldg(gb + k0 + j - i);
        __syncthreads();

        // S = Q K^T
        float acc[4][4];
        #pragma unroll
        for (int i = 0; i < 4; i++)
            #pragma unroll
            for (int j = 0; j < 4; j++) acc[i][j] = 0.f;
        #pragma unroll
        for (int d4 = 0; d4 < 64; d4 += 4) {
            float qv[4][4], kv[4][4];
            #pragma unroll
            for (int i = 0; i < 4; i++)
                *(float4*)qv[i] = *(const float4*)&Qs[(((ty << 2) + i) << 6) + d4];
            #pragma unroll
            for (int dd = 0; dd < 4; dd++)
                *(float4*)kv[dd] = *(const float4*)&KP[((d4 + dd) << 6) + (tx << 2)];
            #pragma unroll
            for (int i = 0; i < 4; i++)
                #pragma unroll
                for (int j = 0; j < 4; j++)
                    acc[i][j] += qv[i][0] * kv[0][j] + qv[i][1] * kv[1][j]
                               + qv[i][2] * kv[2][j] + qv[i][3] * kv[3][j];
        }
        #pragma unroll
        for (int i = 0; i < 4; i++)
            #pragma unroll
            for (int j = 0; j < 4; j++) acc[i][j] += bf[i][j];

        // online softmax (row stats across the 16 tx lanes)
        #pragma unroll
        for (int i = 0; i < 4; i++) {
            float rm = fmaxf(fmaxf(acc[i][0], acc[i][1]), fmaxf(acc[i][2], acc[i][3]));
            rm = fmaxf(rm, __shfl_xor_sync(0xffffffffu, rm, 8, 16));
            rm = fmaxf(rm, __shfl_xor_sync(0xffffffffu, rm, 4, 16));
            rm = fmaxf(rm, __shfl_xor_sync(0xffffffffu, rm, 2, 16));
            rm = fmaxf(rm, __shfl_xor_sync(0xffffffffu, rm, 1, 16));
            float newm  = fmaxf(m_i[i], rm);
            float scale = __expf(m_i[i] - newm);
            m_i[i] = newm;
            float rs = 0.f;
            #pragma unroll
            for (int j = 0; j < 4; j++) {
                acc[i][j] = __expf(acc[i][j] - newm);
                rs += acc[i][j];
            }
            rs += __shfl_xor_sync(0xffffffffu, rs, 8, 16);
            rs += __shfl_xor_sync(0xffffffffu, rs, 4, 16);
            rs += __shfl_xor_sync(0xffffffffu, rs, 2, 16);
            rs += __shfl_xor_sync(0xffffffffu, rs, 1, 16);
            l_i[i] = l_i[i] * scale + rs;
            #pragma unroll
            for (int j = 0; j < 4; j++) O[i][j] *= scale;
        }

        __syncthreads();   // everyone done reading KP (as K^T)
        #pragma unroll
        for (int i = 0; i < 4; i++)
            *(float4*)&KP[(((ty << 2) + i) << 6) + (tx << 2)] =
                make_float4(acc[i][0], acc[i][1], acc[i][2], acc[i][3]);
        __syncthreads();

        // O += P @ V
        #pragma unroll
        for (int c4 = 0; c4 < 64; c4 += 4) {
            float pv[4][4], vv[4][4];
            #pragma unroll
            for (int i = 0; i < 4; i++)
                *(float4*)pv[i] = *(const float4*)&KP[(((ty << 2) + i) << 6) + c4];
            #pragma unroll
            for (int cc = 0; cc < 4; cc++)
                *(float4*)vv[cc] = *(const float4*)&Vs[((c4 + cc) << 6) + (tx << 2)];
            #pragma unroll
            for (int i = 0; i < 4; i++)
                #pragma unroll
                for (int j = 0; j < 4; j++)
                    O[i][j] += pv[i][0] * vv[0][j] + pv[i][1] * vv[1][j]
                             + pv[i][2] * vv[2][j] + pv[i][3] * vv[3][j];
        }
    }

    // epilogue: normalize and store to g_ai[b][s][h*64+d]
    #pragma unroll
    for (int i = 0; i < 4; i++) {
        float inv = 1.f / l_i[i];
        int row = q0 + (ty << 2) + i;
        float4 o4 = make_float4(O[i][0] * inv, O[i][1] * inv, O[i][2] * inv, O[i][3] * inv);
        *(float4*)&g_ai[((size_t)b * SEQ + row) * INNER + h * DHEAD + (tx << 2)] = o4;
    }
}

// ---------------------------------------------------------------------------
extern "C" void kernel_launch(void* const* d_in, const int* in_sizes, int n_in,
                              void* d_out, int out_size)
{
    const float* hidden = (const float*)d_in[0];   // [2,2048,1024]
    const float* w_qkv  = (const float*)d_in[1];   // [1024,3072]
    const float* w_o    = (const float*)d_in[2];   // [1024,1024]
    const float* table  = (const float*)d_in[3];   // [32,16]
    float* out = (float*)d_out;

    float *qkv_ptr = nullptr, *ai_ptr = nullptr;
    cudaGetSymbolAddress((void**)&qkv_ptr, g_qkv);
    cudaGetSymbolAddress((void**)&ai_ptr,  g_ai);

    // 1) per-delta bias table
    bias_fill_kernel<<<16, 256>>>(table);

    // 2) position_bias output (second region of d_out)
    bias_write_kernel<<<dim3(SEQ, NHEADS), 512>>>(out + (size_t)BATCH * SEQ * DMODEL);

    // 3) QKV projection: [4096,1024] @ [1024,3072]
    sgemm128_kernel<<<dim3(QKV3 / 128, (BATCH * SEQ) / 128), 256>>>(
        hidden, w_qkv, qkv_ptr, BATCH * SEQ, QKV3, DMODEL);

    // 4) fused attention
    attn_kernel<<<dim3(SEQ / 64, NHEADS, BATCH), 256>>>();

    // 5) output projection: [4096,1024] @ [1024,1024] -> first region of d_out
    sgemm128_kernel<<<dim3(DMODEL / 128, (BATCH * SEQ) / 128), 256>>>(
        ai_ptr, w_o, out, BATCH * SEQ, DMODEL, DMODEL);
}